// round 2
// baseline (speedup 1.0000x reference)
#include <cuda_runtime.h>
#include <math.h>

#define BATCH   131072
#define FRAME   267
#define H1      512
#define LATENT  256
#define KCODES  1024

// ---------------- scratch (allocation-free: __device__ globals) ----------------
__device__ float  g_bufA[BATCH * H1];       // 256 MiB
__device__ float  g_bufB[BATCH * H1];       // 256 MiB
__device__ float  g_mu[BATCH * LATENT];     // 128 MiB
__device__ float  g_quant[BATCH * LATENT];  // 128 MiB
__device__ float  g_embT[KCODES * LATENT];  // 1 MiB   embed^T  [k][l]
__device__ float  g_enorm[KCODES];
__device__ int    g_ind[BATCH];
__device__ unsigned g_counts[KCODES];
__device__ double g_loss;

// ---------------- init: zero the per-launch accumulators ----------------
__global__ void init_kernel() {
    int t = threadIdx.x;
    if (t < KCODES) g_counts[t] = 0u;
    if (t == 0) g_loss = 0.0;
}

// ---------------- transpose embed + code norms ----------------
// grid: KCODES blocks, 256 threads (one block per code k)
__global__ void transpose_enorm_kernel(const float* __restrict__ embed) {
    int k = blockIdx.x;
    int l = threadIdx.x;                 // 0..255
    float v = embed[l * KCODES + k];
    g_embT[k * LATENT + l] = v;
    __shared__ float red[256];
    red[l] = v * v;
    __syncthreads();
    for (int s = 128; s > 0; s >>= 1) {
        if (l < s) red[l] += red[l + s];
        __syncthreads();
    }
    if (l == 0) g_enorm[k] = red[0];
}

// ---------------- SGEMM: C = act([A0|A1] @ W + bias) ----------------
// A rows: cols [0,K0) from A0, cols [K0,K0+K1) from A1. W row-major [K,N].
// tiles: 128x128x8, 256 threads, 8x8 per thread. M fixed = BATCH (mult of 128).
__global__ __launch_bounds__(256)
void sgemm_kernel(const float* __restrict__ A0, int K0,
                  const float* __restrict__ A1, int K1,
                  const float* __restrict__ W, const float* __restrict__ bias,
                  float* __restrict__ C, int N, int relu)
{
    const int K = K0 + K1;
    __shared__ float As[8][132];
    __shared__ float Bs[8][128];

    const int tid = threadIdx.x;
    const int tx = tid & 15, ty = tid >> 4;
    const int rowBlk = blockIdx.y * 128;
    const int colBlk = blockIdx.x * 128;

    const int la_k = tid & 7, la_m = tid >> 3;     // A: 8 consecutive k per row chunk
    const int lb_n = tid & 127, lb_k0 = tid >> 7;  // B: coalesced over n

    float acc[8][8];
    #pragma unroll
    for (int i = 0; i < 8; i++)
        #pragma unroll
        for (int j = 0; j < 8; j++) acc[i][j] = 0.f;

    for (int kt = 0; kt < K; kt += 8) {
        #pragma unroll
        for (int j = 0; j < 4; j++) {
            int m = la_m + j * 32;
            int kk = kt + la_k;
            float v = 0.f;
            if (kk < K) {
                int gm = rowBlk + m;
                v = (kk < K0) ? A0[gm * K0 + kk] : A1[gm * K1 + (kk - K0)];
            }
            As[la_k][m] = v;
        }
        #pragma unroll
        for (int j = 0; j < 4; j++) {
            int kk = kt + lb_k0 + j * 2;
            int gn = colBlk + lb_n;
            float v = 0.f;
            if (kk < K && gn < N) v = W[kk * N + gn];
            Bs[lb_k0 + j * 2][lb_n] = v;
        }
        __syncthreads();
        #pragma unroll
        for (int k = 0; k < 8; k++) {
            float a[8], b[8];
            #pragma unroll
            for (int i = 0; i < 8; i++) a[i] = As[k][ty * 8 + i];
            #pragma unroll
            for (int i = 0; i < 8; i++) b[i] = Bs[k][tx * 8 + i];
            #pragma unroll
            for (int i = 0; i < 8; i++)
                #pragma unroll
                for (int j = 0; j < 8; j++)
                    acc[i][j] += a[i] * b[j];
        }
        __syncthreads();
    }

    #pragma unroll
    for (int i = 0; i < 8; i++) {
        int gm = rowBlk + ty * 8 + i;
        #pragma unroll
        for (int j = 0; j < 8; j++) {
            int gn = colBlk + tx * 8 + j;
            if (gn < N) {
                float v = acc[i][j] + bias[gn];
                if (relu) v = fmaxf(v, 0.f);
                C[gm * N + gn] = v;
            }
        }
    }
}

// ---------------- VQ: argmin_k ( ||e_k||^2 - 2 mu.e_k ) per row ----------------
// grid: BATCH/128 blocks, 256 threads. Loops 8 code tiles of 128, K=256.
__global__ __launch_bounds__(256)
void vq_kernel(const float* __restrict__ embed)
{
    __shared__ float As[8][132];
    __shared__ float Bs[8][128];
    __shared__ float s_bv[16][128];
    __shared__ int   s_bi[16][128];

    const int tid = threadIdx.x;
    const int tx = tid & 15, ty = tid >> 4;
    const int rowBlk = blockIdx.x * 128;
    const int la_k = tid & 7, la_m = tid >> 3;
    const int lb_n = tid & 127, lb_k0 = tid >> 7;

    float bestv[8];
    int   besti[8];
    #pragma unroll
    for (int i = 0; i < 8; i++) { bestv[i] = 3.4e38f; besti[i] = 0; }

    for (int ct = 0; ct < 8; ct++) {
        const int codeBlk = ct * 128;
        float acc[8][8];
        #pragma unroll
        for (int i = 0; i < 8; i++)
            #pragma unroll
            for (int j = 0; j < 8; j++) acc[i][j] = 0.f;

        for (int kt = 0; kt < LATENT; kt += 8) {
            #pragma unroll
            for (int j = 0; j < 4; j++) {
                int m = la_m + j * 32;
                As[la_k][m] = g_mu[(rowBlk + m) * LATENT + kt + la_k];
            }
            #pragma unroll
            for (int j = 0; j < 4; j++) {
                int kk = kt + lb_k0 + j * 2;
                Bs[lb_k0 + j * 2][lb_n] = embed[kk * KCODES + codeBlk + lb_n];
            }
            __syncthreads();
            #pragma unroll
            for (int k = 0; k < 8; k++) {
                float a[8], b[8];
                #pragma unroll
                for (int i = 0; i < 8; i++) a[i] = As[k][ty * 8 + i];
                #pragma unroll
                for (int i = 0; i < 8; i++) b[i] = Bs[k][tx * 8 + i];
                #pragma unroll
                for (int i = 0; i < 8; i++)
                    #pragma unroll
                    for (int j = 0; j < 8; j++)
                        acc[i][j] += a[i] * b[j];
            }
            __syncthreads();
        }
        #pragma unroll
        for (int j = 0; j < 8; j++) {
            int code = codeBlk + tx * 8 + j;
            float en = g_enorm[code];
            #pragma unroll
            for (int i = 0; i < 8; i++) {
                float d = en - 2.f * acc[i][j];
                if (d < bestv[i]) { bestv[i] = d; besti[i] = code; }  // first-min ties
            }
        }
    }

    #pragma unroll
    for (int i = 0; i < 8; i++) {
        s_bv[tx][ty * 8 + i] = bestv[i];
        s_bi[tx][ty * 8 + i] = besti[i];
    }
    __syncthreads();
    if (tid < 128) {
        float bv = s_bv[0][tid];
        int   bi = s_bi[0][tid];
        #pragma unroll
        for (int t = 1; t < 16; t++) {
            float v = s_bv[t][tid];
            if (v < bv) { bv = v; bi = s_bi[t][tid]; }  // ascending code ranges: first-min
        }
        g_ind[rowBlk + tid] = bi;
        atomicAdd(&g_counts[bi], 1u);
    }
}

// ---------------- gather quantize + loss accumulation ----------------
// grid: BATCH blocks (one row each), 256 threads (one latent dim each)
__global__ void gather_loss_kernel()
{
    int b = blockIdx.x;
    int l = threadIdx.x;
    int k = g_ind[b];
    float q = g_embT[k * LATENT + l];
    float m = g_mu[b * LATENT + l];
    g_quant[b * LATENT + l] = q;
    float d = q - m;
    __shared__ float red[256];
    red[l] = d * d;
    __syncthreads();
    for (int s = 128; s > 0; s >>= 1) {
        if (l < s) red[l] += red[l + s];
        __syncthreads();
    }
    if (l == 0) atomicAdd(&g_loss, (double)red[0]);
}

// ---------------- finalize: loss + perplexity scalars ----------------
__global__ void finalize_kernel(float* __restrict__ out)
{
    __shared__ double red[1024];
    int t = threadIdx.x;
    double p = (double)g_counts[t] / (double)BATCH;
    red[t] = p * log(p + 1e-10);
    __syncthreads();
    for (int s = 512; s > 0; s >>= 1) {
        if (t < s) red[t] += red[t + s];
        __syncthreads();
    }
    if (t == 0) {
        long off = (long)BATCH * FRAME;
        out[off]     = (float)(g_loss / ((double)BATCH * (double)LATENT));
        out[off + 1] = (float)exp(-red[0]);
    }
}

// ---------------- launch ----------------
extern "C" void kernel_launch(void* const* d_in, const int* in_sizes, int n_in,
                              void* d_out, int out_size)
{
    const float* x    = (const float*)d_in[0];
    const float* c    = (const float*)d_in[1];
    const float* W1   = (const float*)d_in[2];  const float* b1  = (const float*)d_in[3];
    const float* W2   = (const float*)d_in[4];  const float* b2  = (const float*)d_in[5];
    const float* W3   = (const float*)d_in[6];  const float* b3  = (const float*)d_in[7];
    const float* Wmu  = (const float*)d_in[8];  const float* bmu = (const float*)d_in[9];
    const float* W4   = (const float*)d_in[10]; const float* b4  = (const float*)d_in[11];
    const float* W5   = (const float*)d_in[12]; const float* b5  = (const float*)d_in[13];
    const float* W6   = (const float*)d_in[14]; const float* b6  = (const float*)d_in[15];
    const float* Wo   = (const float*)d_in[16]; const float* bo  = (const float*)d_in[17];
    const float* embed= (const float*)d_in[18];
    float* out = (float*)d_out;

    float *bufA = nullptr, *bufB = nullptr, *mu = nullptr, *quant = nullptr;
    cudaGetSymbolAddress((void**)&bufA, g_bufA);
    cudaGetSymbolAddress((void**)&bufB, g_bufB);
    cudaGetSymbolAddress((void**)&mu,   g_mu);
    cudaGetSymbolAddress((void**)&quant,g_quant);

    const dim3 blk(256);
    const int MT = BATCH / 128;   // 1024 row tiles

    init_kernel<<<1, 1024>>>();
    transpose_enorm_kernel<<<KCODES, 256>>>(embed);

    // encoder
    sgemm_kernel<<<dim3(4, MT), blk>>>(x, FRAME, c, FRAME, W1, b1, bufA, H1, 1);
    sgemm_kernel<<<dim3(4, MT), blk>>>(bufA, H1, nullptr, 0, W2, b2, bufB, H1, 1);
    sgemm_kernel<<<dim3(4, MT), blk>>>(bufB, H1, nullptr, 0, W3, b3, bufA, H1, 1);
    sgemm_kernel<<<dim3(2, MT), blk>>>(bufA, H1, nullptr, 0, Wmu, bmu, mu, LATENT, 0);

    // vector quantizer
    vq_kernel<<<MT, 256>>>(embed);
    gather_loss_kernel<<<BATCH, 256>>>();

    // decoder
    sgemm_kernel<<<dim3(4, MT), blk>>>(quant, LATENT, c, FRAME, W4, b4, bufA, H1, 1);
    sgemm_kernel<<<dim3(4, MT), blk>>>(bufA, H1, nullptr, 0, W5, b5, bufB, H1, 1);
    sgemm_kernel<<<dim3(4, MT), blk>>>(bufB, H1, nullptr, 0, W6, b6, bufA, H1, 1);
    sgemm_kernel<<<dim3(3, MT), blk>>>(bufA, H1, nullptr, 0, Wo, bo, out, FRAME, 0);

    finalize_kernel<<<1, 1024>>>(out);
}

// round 5
// speedup vs baseline: 2.0380x; 2.0380x over previous
#include <cuda_runtime.h>
#include <cuda_bf16.h>
#include <stdint.h>
#include <math.h>

#define BATCH   131072
#define FRAME   267
#define H1      512
#define LATENT  256
#define KCODES  1024
#define KP1     576      // padded concat K (534 -> 576, 523 -> 576)

// ---------------- weight arena offsets (elements) ----------------
#define OFF_W1   0u
#define OFF_W2   294912u      // 512*576
#define OFF_W3   557056u      // +512*512
#define OFF_WMU  819200u      // +512*512
#define OFF_W4   950272u      // +256*512
#define OFF_W5   1245184u     // +512*576
#define OFF_W6   1507328u     // +512*512
#define OFF_WO   1769472u     // +512*512
#define OFF_EMB  1966080u     // +384*512
#define ARENA    2228224u     // +1024*256

// ---------------- scratch (allocation-free: __device__ globals) ----------------
__device__ __align__(16) __nv_bfloat16 g_wh[ARENA];
__device__ __align__(16) __nv_bfloat16 g_wm[ARENA];
__device__ __align__(16) __nv_bfloat16 g_wl[ARENA];
__device__ __align__(16) __nv_bfloat16 g_sh[(size_t)BATCH * KP1];
__device__ __align__(16) __nv_bfloat16 g_sm[(size_t)BATCH * KP1];
__device__ __align__(16) __nv_bfloat16 g_sl[(size_t)BATCH * KP1];
__device__ __align__(16) __nv_bfloat16 g_xh[(size_t)BATCH * H1];
__device__ __align__(16) __nv_bfloat16 g_xm[(size_t)BATCH * H1];
__device__ __align__(16) __nv_bfloat16 g_xl[(size_t)BATCH * H1];
__device__ __align__(16) __nv_bfloat16 g_yh[(size_t)BATCH * H1];
__device__ __align__(16) __nv_bfloat16 g_ym[(size_t)BATCH * H1];
__device__ __align__(16) __nv_bfloat16 g_yl[(size_t)BATCH * H1];
__device__ __align__(16) float  g_mu[(size_t)BATCH * LATENT];
__device__ __align__(16) float  g_embTf[KCODES * LATENT];   // fp32 embed^T [k][l]
__device__ float  g_enorm[KCODES];
__device__ int    g_ind[BATCH];
__device__ unsigned g_counts[KCODES];
__device__ double g_loss;

// ---------------- helpers ----------------
__device__ __forceinline__ uint32_t smem_u32(const void* p) {
    uint32_t a;
    asm("{ .reg .u64 t; cvta.to.shared.u64 t, %1; cvt.u32.u64 %0, t; }" : "=r"(a) : "l"(p));
    return a;
}
__device__ __forceinline__ void ldsm4(uint32_t* r, uint32_t addr) {
    asm volatile("ldmatrix.sync.aligned.m8n8.x4.shared.b16 {%0,%1,%2,%3}, [%4];"
                 : "=r"(r[0]), "=r"(r[1]), "=r"(r[2]), "=r"(r[3]) : "r"(addr));
}
__device__ __forceinline__ void mma16816(float* c, const uint32_t* a, uint32_t b0, uint32_t b1) {
    asm volatile("mma.sync.aligned.m16n8k16.row.col.f32.bf16.bf16.f32 "
                 "{%0,%1,%2,%3}, {%4,%5,%6,%7}, {%8,%9}, {%0,%1,%2,%3};"
                 : "+f"(c[0]), "+f"(c[1]), "+f"(c[2]), "+f"(c[3])
                 : "r"(a[0]), "r"(a[1]), "r"(a[2]), "r"(a[3]), "r"(b0), "r"(b1));
}
__device__ __forceinline__ uint32_t pack2(__nv_bfloat16 a, __nv_bfloat16 b) {
    return (uint32_t)__bfloat16_as_ushort(a) | ((uint32_t)__bfloat16_as_ushort(b) << 16);
}

// ---------------- init ----------------
__global__ void init_kernel() {
    int t = threadIdx.x;
    if (t < KCODES) g_counts[t] = 0u;
    if (t == 0) g_loss = 0.0;
}

// ---------------- embed norms + fp32 transpose ----------------
__global__ void enorm_kernel(const float* __restrict__ embed) {
    int k = blockIdx.x, l = threadIdx.x;           // k: code, l: latent dim
    float v = embed[l * KCODES + k];
    g_embTf[k * LATENT + l] = v;
    __shared__ float red[256];
    red[l] = v * v;
    __syncthreads();
    for (int s = 128; s > 0; s >>= 1) { if (l < s) red[l] += red[l + s]; __syncthreads(); }
    if (l == 0) g_enorm[k] = red[0];
}

// ---------------- weight prep: W[K][N] fp32 -> Wt[Npad][Kpad] bf16 h/m/l ----------------
__global__ void prep_w(const float* __restrict__ W, int K, int N, int Kpad, int Npad, unsigned off) {
    __shared__ float t[32][33];
    int k0 = blockIdx.x * 32, n0 = blockIdx.y * 32;
    int tx = threadIdx.x, ty = threadIdx.y;  // 32 x 8
    #pragma unroll
    for (int r = 0; r < 32; r += 8) {
        int k = k0 + ty + r, n = n0 + tx;
        t[ty + r][tx] = (k < K && n < N) ? W[(size_t)k * N + n] : 0.f;
    }
    __syncthreads();
    #pragma unroll
    for (int r = 0; r < 32; r += 8) {
        int n = n0 + ty + r, k = k0 + tx;
        if (n < Npad && k < Kpad) {
            float v = t[tx][ty + r];
            __nv_bfloat16 h = __float2bfloat16(v);
            float r1 = v - __bfloat162float(h);
            __nv_bfloat16 m = __float2bfloat16(r1);
            __nv_bfloat16 l = __float2bfloat16(r1 - __bfloat162float(m));
            size_t o = off + (size_t)n * Kpad + k;
            g_wh[o] = h; g_wm[o] = m; g_wl[o] = l;
        }
    }
}

// ---------------- encoder input: [x | c | 0pad] -> bf16 h/m/l ----------------
__global__ void prep_xc(const float* __restrict__ x, const float* __restrict__ c) {
    int b = blockIdx.x, j = threadIdx.x;  // 576 threads
    float v = 0.f;
    if (j < FRAME)            v = x[(size_t)b * FRAME + j];
    else if (j < 2 * FRAME)   v = c[(size_t)b * FRAME + (j - FRAME)];
    __nv_bfloat16 h = __float2bfloat16(v);
    float r1 = v - __bfloat162float(h);
    __nv_bfloat16 m = __float2bfloat16(r1);
    __nv_bfloat16 l = __float2bfloat16(r1 - __bfloat162float(m));
    size_t o = (size_t)b * KP1 + j;
    g_sh[o] = h; g_sm[o] = m; g_sl[o] = l;
}

// ---------------- mu fp32 -> bf16 h/m/l (for VQ GEMM operands) ----------------
__global__ void split_mu() {
    size_t i = (size_t)blockIdx.x * 256 + threadIdx.x;
    float v = g_mu[i];
    __nv_bfloat16 h = __float2bfloat16(v);
    float r1 = v - __bfloat162float(h);
    __nv_bfloat16 m = __float2bfloat16(r1);
    __nv_bfloat16 l = __float2bfloat16(r1 - __bfloat162float(m));
    g_yh[i] = h; g_ym[i] = m; g_yl[i] = l;
}

// =====================================================================
// Tensor-core GEMM: C[128x128 tile] = A[128 x Kpad] @ Wt^T  (Wt: [N][Kpad])
// SPLIT=3: products hh,hm,mh,mm,hl,lh (≈fp32).  SPLIT=2: hh,hl,lh (≈2^-17).
// MODE 0: relu + split-bf16 out (SPLIT arrays).  MODE 1: fp32 out.
// MODE 2: fp32 out masked to N cols.
// =====================================================================
template<int SPLIT, int MODE>
__global__ __launch_bounds__(256)
void mma_gemm(const __nv_bfloat16* __restrict__ A0, const __nv_bfloat16* __restrict__ A1,
              const __nv_bfloat16* __restrict__ A2, int Kpad, unsigned woff,
              const float* __restrict__ bias, int N,
              __nv_bfloat16* __restrict__ O0, __nv_bfloat16* __restrict__ O1,
              __nv_bfloat16* __restrict__ O2, float* __restrict__ Of, int ldo)
{
    extern __shared__ __align__(16) char smem[];
    const uint32_t sb = smem_u32(smem);
    const int tid = threadIdx.x, lane = tid & 31, wid = tid >> 5;
    const int warp_m = wid & 3, warp_n = wid >> 2;
    const int rowBlk = blockIdx.y * 128, colBlk = blockIdx.x * 128;
    constexpr int TILE = 128 * 72 * 2;          // 18432 bytes per split tile
    const uint32_t OA = 512;
    const uint32_t OB = 512 + (uint32_t)SPLIT * TILE;
    float* sbias = (float*)smem;

    if (tid < 128) {
        int gn = colBlk + tid;
        sbias[tid] = (gn < N) ? bias[gn] : 0.f;
    }

    float acc[2][8][4];
    #pragma unroll
    for (int a = 0; a < 2; a++)
        #pragma unroll
        for (int b = 0; b < 8; b++)
            #pragma unroll
            for (int d = 0; d < 4; d++) acc[a][b][d] = 0.f;

    const __nv_bfloat16* Aarr[3] = {A0, A1, A2};

    const int a_row  = (lane & 7) + ((lane >> 3) & 1) * 8;
    const int a_koff = ((lane >> 4) & 1) * 8;
    const int b_row  = (lane & 7) + ((lane >> 4) & 1) * 8;
    const int b_koff = ((lane >> 3) & 1) * 8;

    const int nch = Kpad >> 6;
    for (int kc = 0; kc < nch; kc++) {
        #pragma unroll
        for (int s = 0; s < SPLIT; s++) {
            const __nv_bfloat16* Ap = Aarr[s];
            const __nv_bfloat16* Bp = (s == 0) ? g_wh : (s == 1) ? g_wm : g_wl;
            #pragma unroll
            for (int it = 0; it < 4; it++) {
                int i = tid + it * 256;
                int row = i >> 3, q = i & 7;
                int4 v = *(const int4*)(Ap + (size_t)(rowBlk + row) * Kpad + kc * 64 + q * 8);
                *(int4*)(smem + OA + s * TILE + (row * 72 + q * 8) * 2) = v;
            }
            #pragma unroll
            for (int it = 0; it < 4; it++) {
                int i = tid + it * 256;
                int row = i >> 3, q = i & 7;
                int4 v = *(const int4*)(Bp + woff + (size_t)(colBlk + row) * Kpad + kc * 64 + q * 8);
                *(int4*)(smem + OB + s * TILE + (row * 72 + q * 8) * 2) = v;
            }
        }
        __syncthreads();
        #pragma unroll
        for (int ks = 0; ks < 4; ks++) {
            uint32_t af[3][2][4];
            #pragma unroll
            for (int s = 0; s < SPLIT; s++)
                #pragma unroll
                for (int mt = 0; mt < 2; mt++)
                    ldsm4(af[s][mt], sb + OA + s * TILE +
                          ((warp_m * 32 + mt * 16 + a_row) * 72 + ks * 16 + a_koff) * 2);
            #pragma unroll
            for (int nn = 0; nn < 4; nn++) {
                uint32_t bf[3][4];
                #pragma unroll
                for (int s = 0; s < SPLIT; s++)
                    ldsm4(bf[s], sb + OB + s * TILE +
                          ((warp_n * 64 + nn * 16 + b_row) * 72 + ks * 16 + b_koff) * 2);
                #pragma unroll
                for (int mt = 0; mt < 2; mt++)
                    #pragma unroll
                    for (int g = 0; g < 2; g++) {
                        float* c = acc[mt][nn * 2 + g];
                        mma16816(c, af[0][mt], bf[0][2 * g], bf[0][2 * g + 1]);   // hh
                        mma16816(c, af[0][mt], bf[1][2 * g], bf[1][2 * g + 1]);   // h*lo
                        mma16816(c, af[1][mt], bf[0][2 * g], bf[0][2 * g + 1]);   // lo*h
                        if (SPLIT == 3) {
                            mma16816(c, af[1][mt], bf[1][2 * g], bf[1][2 * g + 1]); // mm
                            mma16816(c, af[0][mt], bf[2][2 * g], bf[2][2 * g + 1]); // hl
                            mma16816(c, af[2][mt], bf[0][2 * g], bf[0][2 * g + 1]); // lh
                        }
                    }
            }
        }
        __syncthreads();
    }

    // epilogue
    #pragma unroll
    for (int mt = 0; mt < 2; mt++) {
        const int row = rowBlk + warp_m * 32 + mt * 16 + (lane >> 2);
        #pragma unroll
        for (int g = 0; g < 8; g++) {
            const int colL = warp_n * 64 + g * 8 + 2 * (lane & 3);
            const int col = colBlk + colL;
            const float bz0 = sbias[colL], bz1 = sbias[colL + 1];
            const float* c = acc[mt][g];
            #pragma unroll
            for (int hf = 0; hf < 2; hf++) {
                const int r = row + hf * 8;
                float v0 = c[hf * 2] + bz0, v1 = c[hf * 2 + 1] + bz1;
                if (MODE == 0) {
                    v0 = fmaxf(v0, 0.f); v1 = fmaxf(v1, 0.f);
                    __nv_bfloat16 h0 = __float2bfloat16(v0), h1 = __float2bfloat16(v1);
                    float r0 = v0 - __bfloat162float(h0), r1 = v1 - __bfloat162float(h1);
                    __nv_bfloat16 m0 = __float2bfloat16(r0), m1 = __float2bfloat16(r1);
                    size_t o = (size_t)r * ldo + col;
                    *(uint32_t*)(O0 + o) = pack2(h0, h1);
                    *(uint32_t*)(O1 + o) = pack2(m0, m1);
                    if (SPLIT == 3) {
                        __nv_bfloat16 l0 = __float2bfloat16(r0 - __bfloat162float(m0));
                        __nv_bfloat16 l1 = __float2bfloat16(r1 - __bfloat162float(m1));
                        *(uint32_t*)(O2 + o) = pack2(l0, l1);
                    }
                } else if (MODE == 1) {
                    float2 v = make_float2(v0, v1);
                    *(float2*)(Of + (size_t)r * ldo + col) = v;
                } else {
                    if (col < N)     Of[(size_t)r * ldo + col] = v0;
                    if (col + 1 < N) Of[(size_t)r * ldo + col + 1] = v1;
                }
            }
        }
    }
}

// =====================================================================
// VQ: per-row argmin over 1024 codes; dist = ||e||^2 - 2 mu.e via split-3 mma
// =====================================================================
__global__ __launch_bounds__(256)
void vq_kernel()
{
    extern __shared__ __align__(16) char smem[];
    const uint32_t sb = smem_u32(smem);
    const int tid = threadIdx.x, lane = tid & 31, wid = tid >> 5;
    const int warp_m = wid & 3, warp_n = wid >> 2;
    const int rowBlk = blockIdx.x * 128;
    constexpr int TILE = 128 * 72 * 2;
    float* senorm = (float*)smem;                    // [128] @0
    float* sval   = (float*)(smem + 512);            // [128]
    int*   sidx   = (int*)(smem + 1024);             // [128]
    const uint32_t OA = 1536;
    const uint32_t OB = 1536 + 3 * TILE;

    const int a_row  = (lane & 7) + ((lane >> 3) & 1) * 8;
    const int a_koff = ((lane >> 4) & 1) * 8;
    const int b_row  = (lane & 7) + ((lane >> 4) & 1) * 8;
    const int b_koff = ((lane >> 3) & 1) * 8;

    float bv[4];
    int   bi[4];
    #pragma unroll
    for (int s = 0; s < 4; s++) { bv[s] = 3.4e38f; bi[s] = 0; }

    for (int ct = 0; ct < 8; ct++) {
        if (tid < 128) senorm[tid] = g_enorm[ct * 128 + tid];
        float acc[2][8][4];
        #pragma unroll
        for (int a = 0; a < 2; a++)
            #pragma unroll
            for (int b = 0; b < 8; b++)
                #pragma unroll
                for (int d = 0; d < 4; d++) acc[a][b][d] = 0.f;

        for (int kc = 0; kc < 4; kc++) {
            #pragma unroll
            for (int s = 0; s < 3; s++) {
                const __nv_bfloat16* Ap = (s == 0) ? g_yh : (s == 1) ? g_ym : g_yl;
                const __nv_bfloat16* Bp = (s == 0) ? g_wh : (s == 1) ? g_wm : g_wl;
                #pragma unroll
                for (int it = 0; it < 4; it++) {
                    int i = tid + it * 256;
                    int row = i >> 3, q = i & 7;
                    int4 v = *(const int4*)(Ap + (size_t)(rowBlk + row) * LATENT + kc * 64 + q * 8);
                    *(int4*)(smem + OA + s * TILE + (row * 72 + q * 8) * 2) = v;
                }
                #pragma unroll
                for (int it = 0; it < 4; it++) {
                    int i = tid + it * 256;
                    int row = i >> 3, q = i & 7;
                    int4 v = *(const int4*)(Bp + OFF_EMB + (size_t)(ct * 128 + row) * LATENT + kc * 64 + q * 8);
                    *(int4*)(smem + OB + s * TILE + (row * 72 + q * 8) * 2) = v;
                }
            }
            __syncthreads();
            #pragma unroll
            for (int ks = 0; ks < 4; ks++) {
                uint32_t af[3][2][4];
                #pragma unroll
                for (int s = 0; s < 3; s++)
                    #pragma unroll
                    for (int mt = 0; mt < 2; mt++)
                        ldsm4(af[s][mt], sb + OA + s * TILE +
                              ((warp_m * 32 + mt * 16 + a_row) * 72 + ks * 16 + a_koff) * 2);
                #pragma unroll
                for (int nn = 0; nn < 4; nn++) {
                    uint32_t bf[3][4];
                    #pragma unroll
                    for (int s = 0; s < 3; s++)
                        ldsm4(bf[s], sb + OB + s * TILE +
                              ((warp_n * 64 + nn * 16 + b_row) * 72 + ks * 16 + b_koff) * 2);
                    #pragma unroll
                    for (int mt = 0; mt < 2; mt++)
                        #pragma unroll
                        for (int g = 0; g < 2; g++) {
                            float* c = acc[mt][nn * 2 + g];
                            mma16816(c, af[0][mt], bf[0][2 * g], bf[0][2 * g + 1]);
                            mma16816(c, af[0][mt], bf[1][2 * g], bf[1][2 * g + 1]);
                            mma16816(c, af[1][mt], bf[0][2 * g], bf[0][2 * g + 1]);
                            mma16816(c, af[1][mt], bf[1][2 * g], bf[1][2 * g + 1]);
                            mma16816(c, af[0][mt], bf[2][2 * g], bf[2][2 * g + 1]);
                            mma16816(c, af[2][mt], bf[0][2 * g], bf[0][2 * g + 1]);
                        }
                }
            }
            __syncthreads();
        }

        // argmin epilogue for this code tile
        #pragma unroll
        for (int mt = 0; mt < 2; mt++)
            #pragma unroll
            for (int hf = 0; hf < 2; hf++) {
                const int slot = mt * 2 + hf;
                float v = 3.4e38f; int idx = 0;
                #pragma unroll
                for (int g = 0; g < 8; g++)
                    #pragma unroll
                    for (int j = 0; j < 2; j++) {
                        int colL = warp_n * 64 + g * 8 + 2 * (lane & 3) + j;
                        float d = senorm[colL] - 2.f * acc[mt][g][hf * 2 + j];
                        int code = ct * 128 + colL;
                        if (d < v || (d == v && code < idx)) { v = d; idx = code; }
                    }
                // reduce across the 4 lanes sharing this row
                #pragma unroll
                for (int o = 1; o <= 2; o <<= 1) {
                    float ov = __shfl_xor_sync(0xFFFFFFFFu, v, o);
                    int   oi = __shfl_xor_sync(0xFFFFFFFFu, idx, o);
                    if (ov < v || (ov == v && oi < idx)) { v = ov; idx = oi; }
                }
                const int rowL = warp_m * 32 + mt * 16 + hf * 8 + (lane >> 2);
                if (warp_n == 1 && (lane & 3) == 0) { sval[rowL] = v; sidx[rowL] = idx; }
                // stash for later combine
                if (warp_n == 0 && (lane & 3) == 0) {
                    // temporary keep in bv-compare after syncthreads below
                    // store candidate in registers via slot arrays:
                    // handled after barrier using v/idx kept in 'tmpv/tmpi'
                }
                // keep per-slot candidate in local arrays
                if ((lane & 3) == 0) {
                    // reuse acc slot as scratch is avoided; store to regs:
                }
                // write to per-thread temp arrays:
                // (store below)
                if (warp_n == 0 && (lane & 3) == 0) {
                    // candidate kept in v/idx for combine after sync
                }
                // save candidate
                {
                    // use shared barrier then combine
                }
                // Stage candidate into registers:
                if (warp_n == 0 && (lane & 3) == 0) { /* combine after sync */ }
                __syncthreads();
                if (warp_n == 0 && (lane & 3) == 0) {
                    float ov = sval[rowL]; int oi = sidx[rowL];
                    if (ov < v || (ov == v && oi < idx)) { v = ov; idx = oi; }
                    if (v < bv[slot] || (v == bv[slot] && idx < bi[slot])) { bv[slot] = v; bi[slot] = idx; }
                }
                __syncthreads();
            }
    }

    if (warp_n == 0 && (lane & 3) == 0) {
        #pragma unroll
        for (int mt = 0; mt < 2; mt++)
            #pragma unroll
            for (int hf = 0; hf < 2; hf++) {
                const int slot = mt * 2 + hf;
                const int rowL = warp_m * 32 + mt * 16 + hf * 8 + (lane >> 2);
                g_ind[rowBlk + rowL] = bi[slot];
                atomicAdd(&g_counts[bi[slot]], 1u);
            }
    }
}

// ---------------- gather quantize -> decoder input [q | c | 0pad] + loss ----------------
__global__ void gather_kernel(const float* __restrict__ c) {
    int b = blockIdx.x, j = threadIdx.x;   // 576 threads
    __shared__ float red[256];
    int k = g_ind[b];
    float v = 0.f;
    if (j < LATENT) {
        float q = g_embTf[k * LATENT + j];
        float d = q - g_mu[(size_t)b * LATENT + j];
        red[j] = d * d;
        v = q;
    } else if (j < LATENT + FRAME) {
        v = c[(size_t)b * FRAME + (j - LATENT)];
    }
    __nv_bfloat16 h = __float2bfloat16(v);
    __nv_bfloat16 m = __float2bfloat16(v - __bfloat162float(h));
    size_t o = (size_t)b * KP1 + j;
    g_sh[o] = h; g_sm[o] = m;
    __syncthreads();
    for (int s = 128; s > 0; s >>= 1) { if (j < s) red[j] += red[j + s]; __syncthreads(); }
    if (j == 0) atomicAdd(&g_loss, (double)red[0]);
}

// ---------------- finalize scalars ----------------
__global__ void finalize_kernel(float* __restrict__ out) {
    __shared__ double red[1024];
    int t = threadIdx.x;
    double p = (double)g_counts[t] / (double)BATCH;
    red[t] = p * log(p + 1e-10);
    __syncthreads();
    for (int s = 512; s > 0; s >>= 1) { if (t < s) red[t] += red[t + s]; __syncthreads(); }
    if (t == 0) {
        size_t off = (size_t)BATCH * FRAME;
        out[off]     = (float)(g_loss / ((double)BATCH * (double)LATENT));
        out[off + 1] = (float)exp(-red[0]);
    }
}

// ---------------- launch ----------------
extern "C" void kernel_launch(void* const* d_in, const int* in_sizes, int n_in,
                              void* d_out, int out_size)
{
    const float* x    = (const float*)d_in[0];
    const float* c    = (const float*)d_in[1];
    const float* W1   = (const float*)d_in[2];  const float* b1  = (const float*)d_in[3];
    const float* W2   = (const float*)d_in[4];  const float* b2  = (const float*)d_in[5];
    const float* W3   = (const float*)d_in[6];  const float* b3  = (const float*)d_in[7];
    const float* Wmu  = (const float*)d_in[8];  const float* bmu = (const float*)d_in[9];
    const float* W4   = (const float*)d_in[10]; const float* b4  = (const float*)d_in[11];
    const float* W5   = (const float*)d_in[12]; const float* b5  = (const float*)d_in[13];
    const float* W6   = (const float*)d_in[14]; const float* b6  = (const float*)d_in[15];
    const float* Wo   = (const float*)d_in[16]; const float* bo  = (const float*)d_in[17];
    const float* embed= (const float*)d_in[18];
    float* out = (float*)d_out;

    __nv_bfloat16 *sh, *sm, *sl, *xh, *xm, *xl, *yh, *ym, *yl;
    float* mu;
    cudaGetSymbolAddress((void**)&sh, g_sh);
    cudaGetSymbolAddress((void**)&sm, g_sm);
    cudaGetSymbolAddress((void**)&sl, g_sl);
    cudaGetSymbolAddress((void**)&xh, g_xh);
    cudaGetSymbolAddress((void**)&xm, g_xm);
    cudaGetSymbolAddress((void**)&xl, g_xl);
    cudaGetSymbolAddress((void**)&yh, g_yh);
    cudaGetSymbolAddress((void**)&ym, g_ym);
    cudaGetSymbolAddress((void**)&yl, g_yl);
    cudaGetSymbolAddress((void**)&mu, g_mu);

    const int SM3 = 512 + 6 * 18432;   // 111104
    const int SM2 = 512 + 4 * 18432;   // 74240
    const int SMV = 1536 + 6 * 18432;  // 112128
    cudaFuncSetAttribute((const void*)mma_gemm<3, 0>, cudaFuncAttributeMaxDynamicSharedMemorySize, SM3);
    cudaFuncSetAttribute((const void*)mma_gemm<3, 1>, cudaFuncAttributeMaxDynamicSharedMemorySize, SM3);
    cudaFuncSetAttribute((const void*)mma_gemm<2, 0>, cudaFuncAttributeMaxDynamicSharedMemorySize, SM2);
    cudaFuncSetAttribute((const void*)mma_gemm<2, 2>, cudaFuncAttributeMaxDynamicSharedMemorySize, SM2);
    cudaFuncSetAttribute((const void*)vq_kernel, cudaFuncAttributeMaxDynamicSharedMemorySize, SMV);

    const int MT = BATCH / 128;   // 1024 row tiles
    dim3 tb(32, 8);

    init_kernel<<<1, 1024>>>();
    enorm_kernel<<<KCODES, 256>>>(embed);

    // weight prep (transpose + bf16 3-way split), grid = (Kpad/32, Npad/32)
    prep_w<<<dim3(18, 16), tb>>>(W1,  534, 512,  KP1, 512,  OFF_W1);
    prep_w<<<dim3(16, 16), tb>>>(W2,  512, 512,  512, 512,  OFF_W2);
    prep_w<<<dim3(16, 16), tb>>>(W3,  512, 512,  512, 512,  OFF_W3);
    prep_w<<<dim3(16, 8),  tb>>>(Wmu, 512, 256,  512, 256,  OFF_WMU);
    prep_w<<<dim3(18, 16), tb>>>(W4,  523, 512,  KP1, 512,  OFF_W4);
    prep_w<<<dim3(16, 16), tb>>>(W5,  512, 512,  512, 512,  OFF_W5);
    prep_w<<<dim3(16, 16), tb>>>(W6,  512, 512,  512, 512,  OFF_W6);
    prep_w<<<dim3(16, 12), tb>>>(Wo,  512, 267,  512, 384,  OFF_WO);
    prep_w<<<dim3(8,  32), tb>>>(embed, 256, 1024, 256, 1024, OFF_EMB);

    prep_xc<<<BATCH, KP1>>>(x, c);

    // encoder (split-3: ~fp32-exact so the VQ argmin matches the reference)
    mma_gemm<3, 0><<<dim3(4, MT), 256, SM3>>>(sh, sm, sl, KP1, OFF_W1,  b1,  512, xh, xm, xl, nullptr, 512);
    mma_gemm<3, 0><<<dim3(4, MT), 256, SM3>>>(xh, xm, xl, 512, OFF_W2,  b2,  512, yh, ym, yl, nullptr, 512);
    mma_gemm<3, 0><<<dim3(4, MT), 256, SM3>>>(yh, ym, yl, 512, OFF_W3,  b3,  512, xh, xm, xl, nullptr, 512);
    mma_gemm<3, 1><<<dim3(2, MT), 256, SM3>>>(xh, xm, xl, 512, OFF_WMU, bmu, 256, nullptr, nullptr, nullptr, mu, 256);

    // vector quantizer
    split_mu<<<BATCH * LATENT / 256, 256>>>();
    vq_kernel<<<MT, 256, SMV>>>();
    gather_kernel<<<BATCH, KP1>>>(c);

    // decoder (split-2: error ~1.5e-5 direct to output)
    mma_gemm<2, 0><<<dim3(4, MT), 256, SM2>>>(sh, sm, nullptr, KP1, OFF_W4, b4, 512, xh, xm, nullptr, nullptr, 512);
    mma_gemm<2, 0><<<dim3(4, MT), 256, SM2>>>(xh, xm, nullptr, 512, OFF_W5, b5, 512, yh, ym, nullptr, nullptr, 512);
    mma_gemm<2, 0><<<dim3(4, MT), 256, SM2>>>(yh, ym, nullptr, 512, OFF_W6, b6, 512, xh, xm, nullptr, nullptr, 512);
    mma_gemm<2, 2><<<dim3(3, MT), 256, SM2>>>(xh, xm, nullptr, 512, OFF_WO, bo, 267, nullptr, nullptr, nullptr, out, FRAME);

    finalize_kernel<<<1, 1024>>>(out);
}

// round 7
// speedup vs baseline: 3.3854x; 1.6611x over previous
#include <cuda_runtime.h>
#include <cuda_fp16.h>
#include <stdint.h>
#include <math.h>

#define BATCH   131072
#define FRAME   267
#define H1      512
#define LATENT  256
#define KCODES  1024
#define KP1     576      // padded concat K (534 -> 576, 523 -> 576)

// ---------------- weight arena offsets (elements) ----------------
#define OFF_W1   0u
#define OFF_W2   294912u      // 512*576
#define OFF_W3   557056u      // +512*512
#define OFF_WMU  819200u      // +512*512
#define OFF_W4   950272u      // +256*512
#define OFF_W5   1245184u     // +512*576
#define OFF_W6   1507328u     // +512*512
#define OFF_WO   1769472u     // +512*512
#define OFF_EMB  1966080u     // +384*512
#define ARENA    2228224u     // +1024*256

// ---------------- scratch (allocation-free: __device__ globals) ----------------
__device__ __align__(16) __half g_wh[ARENA];
__device__ __align__(16) __half g_wl[ARENA];
__device__ __align__(16) __half g_sh[(size_t)BATCH * KP1];
__device__ __align__(16) __half g_sl[(size_t)BATCH * KP1];
__device__ __align__(16) __half g_xh[(size_t)BATCH * H1];
__device__ __align__(16) __half g_xl[(size_t)BATCH * H1];
__device__ __align__(16) __half g_yh[(size_t)BATCH * H1];
__device__ __align__(16) __half g_yl[(size_t)BATCH * H1];
__device__ __align__(16) float  g_embTf[KCODES * LATENT];   // fp32 embed^T [k][l]
__device__ float  g_enorm[KCODES];
__device__ int    g_ind[BATCH];
__device__ unsigned g_counts[KCODES];
__device__ double g_loss;

// ---------------- helpers ----------------
__device__ __forceinline__ uint32_t smem_u32(const void* p) {
    uint32_t a;
    asm("{ .reg .u64 t; cvta.to.shared.u64 t, %1; cvt.u32.u64 %0, t; }" : "=r"(a) : "l"(p));
    return a;
}
__device__ __forceinline__ void ldsm4(uint32_t* r, uint32_t addr) {
    asm volatile("ldmatrix.sync.aligned.m8n8.x4.shared.b16 {%0,%1,%2,%3}, [%4];"
                 : "=r"(r[0]), "=r"(r[1]), "=r"(r[2]), "=r"(r[3]) : "r"(addr));
}
__device__ __forceinline__ void mma16816(float* c, const uint32_t* a, uint32_t b0, uint32_t b1) {
    asm volatile("mma.sync.aligned.m16n8k16.row.col.f32.f16.f16.f32 "
                 "{%0,%1,%2,%3}, {%4,%5,%6,%7}, {%8,%9}, {%0,%1,%2,%3};"
                 : "+f"(c[0]), "+f"(c[1]), "+f"(c[2]), "+f"(c[3])
                 : "r"(a[0]), "r"(a[1]), "r"(a[2]), "r"(a[3]), "r"(b0), "r"(b1));
}
__device__ __forceinline__ void cpa16(uint32_t dst, const void* src) {
    asm volatile("cp.async.cg.shared.global [%0], [%1], 16;" :: "r"(dst), "l"(src));
}
#define CPA_COMMIT() asm volatile("cp.async.commit_group;" ::: "memory")
#define CPA_WAIT1()  asm volatile("cp.async.wait_group 1;" ::: "memory")
__device__ __forceinline__ uint32_t pack2(__half a, __half b) {
    return (uint32_t)__half_as_ushort(a) | ((uint32_t)__half_as_ushort(b) << 16);
}
__device__ __forceinline__ void split2(float v, __half& h, __half& l) {
    h = __float2half_rn(v);
    l = __float2half_rn(v - __half2float(h));
}

// ---------------- init ----------------
__global__ void init_kernel() {
    int t = threadIdx.x;
    if (t < KCODES) g_counts[t] = 0u;
    if (t == 0) g_loss = 0.0;
}

// ---------------- embed norms + fp32 transpose ----------------
__global__ void enorm_kernel(const float* __restrict__ embed) {
    int k = blockIdx.x, l = threadIdx.x;           // k: code, l: latent dim
    float v = embed[l * KCODES + k];
    g_embTf[k * LATENT + l] = v;
    __shared__ float red[256];
    red[l] = v * v;
    __syncthreads();
    for (int s = 128; s > 0; s >>= 1) { if (l < s) red[l] += red[l + s]; __syncthreads(); }
    if (l == 0) g_enorm[k] = red[0];
}

// ---------------- weight prep: W[K][N] fp32 -> Wt[Npad][Kpad] fp16 h/l ----------------
__global__ void prep_w(const float* __restrict__ W, int K, int N, int Kpad, int Npad, unsigned off) {
    __shared__ float t[32][33];
    int k0 = blockIdx.x * 32, n0 = blockIdx.y * 32;
    int tx = threadIdx.x, ty = threadIdx.y;  // 32 x 8
    #pragma unroll
    for (int r = 0; r < 32; r += 8) {
        int k = k0 + ty + r, n = n0 + tx;
        t[ty + r][tx] = (k < K && n < N) ? W[(size_t)k * N + n] : 0.f;
    }
    __syncthreads();
    #pragma unroll
    for (int r = 0; r < 32; r += 8) {
        int n = n0 + ty + r, k = k0 + tx;
        if (n < Npad && k < Kpad) {
            __half h, l;
            split2(t[tx][ty + r], h, l);
            size_t o = off + (size_t)n * Kpad + k;
            g_wh[o] = h; g_wl[o] = l;
        }
    }
}

// ---------------- encoder input: [x | c | 0pad] -> fp16 h/l ----------------
__global__ void prep_xc(const float* __restrict__ x, const float* __restrict__ c) {
    int b = blockIdx.x, j = threadIdx.x;  // 576 threads
    float v = 0.f;
    if (j < FRAME)            v = x[(size_t)b * FRAME + j];
    else if (j < 2 * FRAME)   v = c[(size_t)b * FRAME + (j - FRAME)];
    __half h, l;
    split2(v, h, l);
    size_t o = (size_t)b * KP1 + j;
    g_sh[o] = h; g_sl[o] = l;
}

// =====================================================================
// fp16x2 tensor-core GEMM: C[128x128] = A[128 x Kpad] @ Wt^T   (Wt: [Npad][Kpad])
// products hh + hl + lh (fp32 accum) ~= fp32 GEMM.
// MODE 0: relu + fp16-split out.  MODE 1: fp16-split out (no relu).
// MODE 2: fp32 out masked to N cols.
// cp.async 2-stage double buffering.
// =====================================================================
template<int MODE>
__global__ __launch_bounds__(256)
void mma_gemm(const __half* __restrict__ Ah, const __half* __restrict__ Al,
              int Kpad, unsigned woff, const float* __restrict__ bias, int N,
              __half* __restrict__ O0, __half* __restrict__ O1,
              float* __restrict__ Of, int ldo)
{
    extern __shared__ __align__(16) char smem[];
    const uint32_t sb = smem_u32(smem);
    const int tid = threadIdx.x, lane = tid & 31, wid = tid >> 5;
    const int warp_m = wid & 3, warp_n = wid >> 2;
    const int rowBlk = blockIdx.y * 128, colBlk = blockIdx.x * 128;
    constexpr uint32_t TILE = 128 * 72 * 2;      // 18432 B
    const uint32_t OS = 512;                     // after bias
    float* sbias = (float*)smem;

    if (tid < 128) {
        int gn = colBlk + tid;
        sbias[tid] = (gn < N) ? bias[gn] : 0.f;
    }

    const __half* Wh = g_wh + woff;
    const __half* Wl = g_wl + woff;

    // ---- stage loader: tiles {Ah, Al, Bh, Bl} for chunk kc into stage st ----
    auto load_chunk = [&](int kc, int st) {
        uint32_t base = sb + OS + (uint32_t)st * 4 * TILE;
        #pragma unroll
        for (int it = 0; it < 4; it++) {
            int i = tid + it * 256;
            int r = i >> 3, q = i & 7;
            uint32_t dst = base + (uint32_t)(r * 144 + q * 16);
            size_t ga = (size_t)(rowBlk + r) * Kpad + kc * 64 + q * 8;
            size_t gb = (size_t)(colBlk + r) * Kpad + kc * 64 + q * 8;
            cpa16(dst,            Ah + ga);
            cpa16(dst + TILE,     Al + ga);
            cpa16(dst + 2 * TILE, Wh + gb);
            cpa16(dst + 3 * TILE, Wl + gb);
        }
    };

    float acc[2][8][4];
    #pragma unroll
    for (int a = 0; a < 2; a++)
        #pragma unroll
        for (int b = 0; b < 8; b++)
            #pragma unroll
            for (int d = 0; d < 4; d++) acc[a][b][d] = 0.f;

    const int a_row  = (lane & 7) + ((lane >> 3) & 1) * 8;
    const int a_koff = ((lane >> 4) & 1) * 8;
    const int b_row  = (lane & 7) + ((lane >> 4) & 1) * 8;
    const int b_koff = ((lane >> 3) & 1) * 8;

    const int nch = Kpad >> 6;
    load_chunk(0, 0);
    CPA_COMMIT();

    for (int kc = 0; kc < nch; kc++) {
        if (kc + 1 < nch) load_chunk(kc + 1, (kc + 1) & 1);
        CPA_COMMIT();
        CPA_WAIT1();
        __syncthreads();
        const uint32_t stg = sb + OS + (uint32_t)(kc & 1) * 4 * TILE;
        #pragma unroll
        for (int ks = 0; ks < 4; ks++) {
            uint32_t af[2][2][4];
            #pragma unroll
            for (int s = 0; s < 2; s++)
                #pragma unroll
                for (int mt = 0; mt < 2; mt++)
                    ldsm4(af[s][mt], stg + s * TILE +
                          (uint32_t)((warp_m * 32 + mt * 16 + a_row) * 72 + ks * 16 + a_koff) * 2);
            #pragma unroll
            for (int nn = 0; nn < 4; nn++) {
                uint32_t bf[2][4];
                #pragma unroll
                for (int s = 0; s < 2; s++)
                    ldsm4(bf[s], stg + (2 + s) * TILE +
                          (uint32_t)((warp_n * 64 + nn * 16 + b_row) * 72 + ks * 16 + b_koff) * 2);
                #pragma unroll
                for (int mt = 0; mt < 2; mt++)
                    #pragma unroll
                    for (int g = 0; g < 2; g++) {
                        float* c = acc[mt][nn * 2 + g];
                        mma16816(c, af[0][mt], bf[0][2 * g], bf[0][2 * g + 1]);   // hh
                        mma16816(c, af[0][mt], bf[1][2 * g], bf[1][2 * g + 1]);   // hl
                        mma16816(c, af[1][mt], bf[0][2 * g], bf[0][2 * g + 1]);   // lh
                    }
            }
        }
        __syncthreads();
    }

    // epilogue
    #pragma unroll
    for (int mt = 0; mt < 2; mt++) {
        const int row = rowBlk + warp_m * 32 + mt * 16 + (lane >> 2);
        #pragma unroll
        for (int g = 0; g < 8; g++) {
            const int colL = warp_n * 64 + g * 8 + 2 * (lane & 3);
            const int col = colBlk + colL;
            const float bz0 = sbias[colL], bz1 = sbias[colL + 1];
            const float* c = acc[mt][g];
            #pragma unroll
            for (int hf = 0; hf < 2; hf++) {
                const int r = row + hf * 8;
                float v0 = c[hf * 2] + bz0, v1 = c[hf * 2 + 1] + bz1;
                if (MODE == 0 || MODE == 1) {
                    if (MODE == 0) { v0 = fmaxf(v0, 0.f); v1 = fmaxf(v1, 0.f); }
                    __half h0, l0, h1, l1;
                    split2(v0, h0, l0);
                    split2(v1, h1, l1);
                    size_t o = (size_t)r * ldo + col;
                    *(uint32_t*)(O0 + o) = pack2(h0, h1);
                    *(uint32_t*)(O1 + o) = pack2(l0, l1);
                } else {
                    if (col < N)     Of[(size_t)r * ldo + col] = v0;
                    if (col + 1 < N) Of[(size_t)r * ldo + col + 1] = v1;
                }
            }
        }
    }
}

// =====================================================================
// VQ: per-row argmin over 1024 codes; dist = ||e||^2 - 2 mu.e
// mu A-tiles (2 splits x 4 chunks) resident in smem; embed B double-buffered.
// =====================================================================
__global__ __launch_bounds__(256)
void vq_kernel()
{
    extern __shared__ __align__(16) char smem[];
    const uint32_t sb = smem_u32(smem);
    const int tid = threadIdx.x, lane = tid & 31, wid = tid >> 5;
    const int warp_m = wid & 3, warp_n = wid >> 2;
    const int rowBlk = blockIdx.x * 128;
    constexpr uint32_t TILE = 128 * 72 * 2;
    float* sval = (float*)smem;                    // [128]
    int*   sidx = (int*)(smem + 512);              // [128]
    const uint32_t OA = 1024;                      // A: [s][kc] 8 tiles
    const uint32_t OB = OA + 8 * TILE;             // B: 2 stages x {h,l}

    const int a_row  = (lane & 7) + ((lane >> 3) & 1) * 8;
    const int a_koff = ((lane >> 4) & 1) * 8;
    const int b_row  = (lane & 7) + ((lane >> 4) & 1) * 8;
    const int b_koff = ((lane >> 3) & 1) * 8;

    // ---- preload resident A (mu splits), all 4 chunks ----
    #pragma unroll
    for (int kc = 0; kc < 4; kc++)
        #pragma unroll
        for (int it = 0; it < 4; it++) {
            int i = tid + it * 256;
            int r = i >> 3, q = i & 7;
            size_t ga = (size_t)(rowBlk + r) * LATENT + kc * 64 + q * 8;
            uint32_t dst = sb + OA + (uint32_t)kc * TILE + (uint32_t)(r * 144 + q * 16);
            cpa16(dst,            g_yh + ga);
            cpa16(dst + 4 * TILE, g_yl + ga);
        }
    CPA_COMMIT();

    auto load_b = [&](int ct, int kc, int st) {
        uint32_t base = sb + OB + (uint32_t)st * 2 * TILE;
        #pragma unroll
        for (int it = 0; it < 4; it++) {
            int i = tid + it * 256;
            int r = i >> 3, q = i & 7;
            size_t gb = OFF_EMB + (size_t)(ct * 128 + r) * LATENT + kc * 64 + q * 8;
            uint32_t dst = base + (uint32_t)(r * 144 + q * 16);
            cpa16(dst,        g_wh + gb);
            cpa16(dst + TILE, g_wl + gb);
        }
    };

    load_b(0, 0, 0);
    CPA_COMMIT();

    float bv[4];
    int   bi[4];
    #pragma unroll
    for (int s = 0; s < 4; s++) { bv[s] = 3.4e38f; bi[s] = 0; }

    int gstep = 0;
    for (int ct = 0; ct < 8; ct++) {
        float acc[2][8][4];
        #pragma unroll
        for (int a = 0; a < 2; a++)
            #pragma unroll
            for (int b = 0; b < 8; b++)
                #pragma unroll
                for (int d = 0; d < 4; d++) acc[a][b][d] = 0.f;

        for (int kc = 0; kc < 4; kc++) {
            int nct = (kc + 1 < 4) ? ct : ct + 1;
            int nkc = (kc + 1 < 4) ? kc + 1 : 0;
            if (nct < 8) load_b(nct, nkc, (gstep + 1) & 1);
            CPA_COMMIT();
            CPA_WAIT1();
            __syncthreads();
            const uint32_t stg = sb + OB + (uint32_t)(gstep & 1) * 2 * TILE;
            #pragma unroll
            for (int ks = 0; ks < 4; ks++) {
                uint32_t af[2][2][4];
                #pragma unroll
                for (int s = 0; s < 2; s++)
                    #pragma unroll
                    for (int mt = 0; mt < 2; mt++)
                        ldsm4(af[s][mt], sb + OA + (uint32_t)(s * 4 + kc) * TILE +
                              (uint32_t)((warp_m * 32 + mt * 16 + a_row) * 72 + ks * 16 + a_koff) * 2);
                #pragma unroll
                for (int nn = 0; nn < 4; nn++) {
                    uint32_t bf[2][4];
                    #pragma unroll
                    for (int s = 0; s < 2; s++)
                        ldsm4(bf[s], stg + s * TILE +
                              (uint32_t)((warp_n * 64 + nn * 16 + b_row) * 72 + ks * 16 + b_koff) * 2);
                    #pragma unroll
                    for (int mt = 0; mt < 2; mt++)
                        #pragma unroll
                        for (int g = 0; g < 2; g++) {
                            float* c = acc[mt][nn * 2 + g];
                            mma16816(c, af[0][mt], bf[0][2 * g], bf[0][2 * g + 1]);
                            mma16816(c, af[0][mt], bf[1][2 * g], bf[1][2 * g + 1]);
                            mma16816(c, af[1][mt], bf[0][2 * g], bf[0][2 * g + 1]);
                        }
                }
            }
            gstep++;
            __syncthreads();
        }

        // ---- argmin epilogue for this code tile ----
        #pragma unroll
        for (int mt = 0; mt < 2; mt++)
            #pragma unroll
            for (int hf = 0; hf < 2; hf++) {
                const int slot = mt * 2 + hf;
                const int rowL = warp_m * 32 + mt * 16 + hf * 8 + (lane >> 2);
                float v = 3.4e38f; int idx = 0;
                #pragma unroll
                for (int g = 0; g < 8; g++)
                    #pragma unroll
                    for (int j = 0; j < 2; j++) {
                        int colL = warp_n * 64 + g * 8 + 2 * (lane & 3) + j;
                        int code = ct * 128 + colL;
                        float d = g_enorm[code] - 2.f * acc[mt][g][hf * 2 + j];
                        if (d < v || (d == v && code < idx)) { v = d; idx = code; }
                    }
                #pragma unroll
                for (int o = 1; o <= 2; o <<= 1) {
                    float ov = __shfl_xor_sync(0xFFFFFFFFu, v, o);
                    int   oi = __shfl_xor_sync(0xFFFFFFFFu, idx, o);
                    if (ov < v || (ov == v && oi < idx)) { v = ov; idx = oi; }
                }
                if (warp_n == 1 && (lane & 3) == 0) { sval[rowL] = v; sidx[rowL] = idx; }
                __syncthreads();
                if (warp_n == 0 && (lane & 3) == 0) {
                    float ov = sval[rowL]; int oi = sidx[rowL];
                    if (ov < v || (ov == v && oi < idx)) { v = ov; idx = oi; }
                    if (v < bv[slot] || (v == bv[slot] && idx < bi[slot])) { bv[slot] = v; bi[slot] = idx; }
                }
                __syncthreads();
            }
    }

    if (warp_n == 0 && (lane & 3) == 0) {
        #pragma unroll
        for (int mt = 0; mt < 2; mt++)
            #pragma unroll
            for (int hf = 0; hf < 2; hf++) {
                const int slot = mt * 2 + hf;
                const int rowL = warp_m * 32 + mt * 16 + hf * 8 + (lane >> 2);
                g_ind[rowBlk + rowL] = bi[slot];
                atomicAdd(&g_counts[bi[slot]], 1u);
            }
    }
}

// ---------------- gather quantize -> decoder input [q | c | 0pad] + loss ----------------
__global__ void gather_kernel(const float* __restrict__ c) {
    int b = blockIdx.x, j = threadIdx.x;   // 576 threads
    __shared__ float red[256];
    int k = g_ind[b];
    float v = 0.f;
    if (j < LATENT) {
        size_t om = (size_t)b * LATENT + j;
        float m = __half2float(g_yh[om]) + __half2float(g_yl[om]);
        float q = g_embTf[k * LATENT + j];
        float d = q - m;
        red[j] = d * d;
        v = q;
    } else if (j < LATENT + FRAME) {
        v = c[(size_t)b * FRAME + (j - LATENT)];
    }
    __half h, l;
    split2(v, h, l);
    size_t o = (size_t)b * KP1 + j;
    g_sh[o] = h; g_sl[o] = l;
    __syncthreads();
    for (int s = 128; s > 0; s >>= 1) { if (j < s) red[j] += red[j + s]; __syncthreads(); }
    if (j == 0) atomicAdd(&g_loss, (double)red[0]);
}

// ---------------- finalize scalars ----------------
__global__ void finalize_kernel(float* __restrict__ out) {
    __shared__ double red[1024];
    int t = threadIdx.x;
    double p = (double)g_counts[t] / (double)BATCH;
    red[t] = p * log(p + 1e-10);
    __syncthreads();
    for (int s = 512; s > 0; s >>= 1) { if (t < s) red[t] += red[t + s]; __syncthreads(); }
    if (t == 0) {
        size_t off = (size_t)BATCH * FRAME;
        out[off]     = (float)(g_loss / ((double)BATCH * (double)LATENT));
        out[off + 1] = (float)exp(-red[0]);
    }
}

// ---------------- launch ----------------
extern "C" void kernel_launch(void* const* d_in, const int* in_sizes, int n_in,
                              void* d_out, int out_size)
{
    const float* x    = (const float*)d_in[0];
    const float* c    = (const float*)d_in[1];
    const float* W1   = (const float*)d_in[2];  const float* b1  = (const float*)d_in[3];
    const float* W2   = (const float*)d_in[4];  const float* b2  = (const float*)d_in[5];
    const float* W3   = (const float*)d_in[6];  const float* b3  = (const float*)d_in[7];
    const float* Wmu  = (const float*)d_in[8];  const float* bmu = (const float*)d_in[9];
    const float* W4   = (const float*)d_in[10]; const float* b4  = (const float*)d_in[11];
    const float* W5   = (const float*)d_in[12]; const float* b5  = (const float*)d_in[13];
    const float* W6   = (const float*)d_in[14]; const float* b6  = (const float*)d_in[15];
    const float* Wo   = (const float*)d_in[16]; const float* bo  = (const float*)d_in[17];
    const float* embed= (const float*)d_in[18];
    float* out = (float*)d_out;

    __half *sh, *sl, *xh, *xl, *yh, *yl;
    cudaGetSymbolAddress((void**)&sh, g_sh);
    cudaGetSymbolAddress((void**)&sl, g_sl);
    cudaGetSymbolAddress((void**)&xh, g_xh);
    cudaGetSymbolAddress((void**)&xl, g_xl);
    cudaGetSymbolAddress((void**)&yh, g_yh);
    cudaGetSymbolAddress((void**)&yl, g_yl);

    const int SMG = 512 + 2 * 4 * 18432;               // 147968
    const int SMV = 1024 + 8 * 18432 + 2 * 2 * 18432;  // 222208
    cudaFuncSetAttribute((const void*)mma_gemm<0>, cudaFuncAttributeMaxDynamicSharedMemorySize, SMG);
    cudaFuncSetAttribute((const void*)mma_gemm<1>, cudaFuncAttributeMaxDynamicSharedMemorySize, SMG);
    cudaFuncSetAttribute((const void*)mma_gemm<2>, cudaFuncAttributeMaxDynamicSharedMemorySize, SMG);
    cudaFuncSetAttribute((const void*)vq_kernel,   cudaFuncAttributeMaxDynamicSharedMemorySize, SMV);

    const int MT = BATCH / 128;   // 1024 row tiles
    dim3 tb(32, 8);

    init_kernel<<<1, 1024>>>();
    enorm_kernel<<<KCODES, 256>>>(embed);

    // weight prep (transpose + fp16 2-way split), grid = (Kpad/32, Npad/32)
    prep_w<<<dim3(18, 16), tb>>>(W1,  534, 512,  KP1, 512,  OFF_W1);
    prep_w<<<dim3(16, 16), tb>>>(W2,  512, 512,  512, 512,  OFF_W2);
    prep_w<<<dim3(16, 16), tb>>>(W3,  512, 512,  512, 512,  OFF_W3);
    prep_w<<<dim3(16, 8),  tb>>>(Wmu, 512, 256,  512, 256,  OFF_WMU);
    prep_w<<<dim3(18, 16), tb>>>(W4,  523, 512,  KP1, 512,  OFF_W4);
    prep_w<<<dim3(16, 16), tb>>>(W5,  512, 512,  512, 512,  OFF_W5);
    prep_w<<<dim3(16, 16), tb>>>(W6,  512, 512,  512, 512,  OFF_W6);
    prep_w<<<dim3(16, 12), tb>>>(Wo,  512, 267,  512, 384,  OFF_WO);
    prep_w<<<dim3(8,  32), tb>>>(embed, 256, 1024, 256, 1024, OFF_EMB);

    prep_xc<<<BATCH, KP1>>>(x, c);

    // encoder
    mma_gemm<0><<<dim3(4, MT), 256, SMG>>>(sh, sl, KP1, OFF_W1,  b1,  512, xh, xl, nullptr, 512);
    mma_gemm<0><<<dim3(4, MT), 256, SMG>>>(xh, xl, 512, OFF_W2,  b2,  512, yh, yl, nullptr, 512);
    mma_gemm<0><<<dim3(4, MT), 256, SMG>>>(yh, yl, 512, OFF_W3,  b3,  512, xh, xl, nullptr, 512);
    mma_gemm<1><<<dim3(2, MT), 256, SMG>>>(xh, xl, 512, OFF_WMU, bmu, 256, yh, yl, nullptr, 256);  // mu splits

    // vector quantizer + gather/loss (rebuilds g_s as decoder input)
    vq_kernel<<<MT, 256, SMV>>>();
    gather_kernel<<<BATCH, KP1>>>(c);

    // decoder
    mma_gemm<0><<<dim3(4, MT), 256, SMG>>>(sh, sl, KP1, OFF_W4, b4, 512, xh, xl, nullptr, 512);
    mma_gemm<0><<<dim3(4, MT), 256, SMG>>>(xh, xl, 512, OFF_W5, b5, 512, yh, yl, nullptr, 512);
    mma_gemm<0><<<dim3(4, MT), 256, SMG>>>(yh, yl, 512, OFF_W6, b6, 512, xh, xl, nullptr, 512);
    mma_gemm<2><<<dim3(3, MT), 256, SMG>>>(xh, xl, 512, OFF_WO, bo, 267, nullptr, nullptr, out, FRAME);

    finalize_kernel<<<1, 1024>>>(out);
}